// round 6
// baseline (speedup 1.0000x reference)
#include <cuda_runtime.h>
#include <cstdint>

// Graph_Learn, symmetric-triangle 2-pass + packed f32x2.
// K1 computes tmpS = exp(relu(sum_f a_f*|x_i,f - x_j,f|)) on upper trapezoids
// and mirrors (bitwise-exact symmetry). K2 normalizes by row sums
// (== reference's column sums by symmetry); warp = 4 rows, MLP=8, no barriers.

#define Vn 256
#define Fn 64
#define TR 4            // tile rows (K1)
#define PAD 68          // floats per smem row (17 * 16B, odd quad stride)

#define SMEM_XS   (Vn * PAD)
#define SMEM_AS   (SMEM_XS)           // a[64]
#define SMEM_FLOATS (SMEM_AS + Fn)
#define SMEM_BYTES  (SMEM_FLOATS * 4)

typedef unsigned long long u64;

__device__ float g_tmp[32u * Vn * Vn];   // 8 MB scratch (BT <= 32)

__device__ __forceinline__ u64 f2add(u64 a, u64 b) {
    u64 d; asm("add.rn.f32x2 %0,%1,%2;" : "=l"(d) : "l"(a), "l"(b)); return d;
}
__device__ __forceinline__ u64 f2fma(u64 a, u64 b, u64 c) {
    u64 d; asm("fma.rn.f32x2 %0,%1,%2,%3;" : "=l"(d) : "l"(a), "l"(b), "l"(c)); return d;
}
__device__ __forceinline__ u64 f2abs(u64 a) {
    u64 d; asm("and.b64 %0,%1,0x7FFFFFFF7FFFFFFF;" : "=l"(d) : "l"(a)); return d;
}
__device__ __forceinline__ u64 packf2(float lo, float hi) {
    u64 d; asm("mov.b64 %0,{%1,%2};" : "=l"(d) : "f"(lo), "f"(hi)); return d;
}
__device__ __forceinline__ void unpackf2(u64 v, float& lo, float& hi) {
    asm("mov.b64 {%0,%1},%2;" : "=f"(lo), "=f"(hi) : "l"(v));
}
__device__ __forceinline__ void lds_2x64(uint32_t addr, u64& p0, u64& p1) {
    asm volatile("ld.shared.v2.u64 {%0,%1},[%2];" : "=l"(p0), "=l"(p1) : "r"(addr));
}

__device__ __forceinline__ void tile_rows(uint32_t xs_sh, int i0, int f0,
                                          const u64* nxj, const u64* av, u64* acc)
{
    #pragma unroll
    for (int r = 0; r < TR; ++r) {
        const uint32_t base = xs_sh + (uint32_t)(((i0 + r) * PAD + f0) * 4);
        u64 xi[8];
        lds_2x64(base +  0, xi[0], xi[1]);   // uniform broadcast LDS.128
        lds_2x64(base + 16, xi[2], xi[3]);
        lds_2x64(base + 32, xi[4], xi[5]);
        lds_2x64(base + 48, xi[6], xi[7]);
        u64 s = acc[r];
        #pragma unroll
        for (int k = 0; k < 8; ++k) {
            u64 d = f2abs(f2add(xi[k], nxj[k]));   // ADD2 + 2xLOP3
            s = f2fma(d, av[k], s);                // FFMA2
        }
        acc[r] = s;
    }
}

__device__ __forceinline__ void store_tile(const u64* acc, int bt, int i0, int j)
{
    float f[TR];
    #pragma unroll
    for (int r = 0; r < TR; ++r) {
        float lo, hi; unpackf2(acc[r], lo, hi);
        f[r] = __expf(fmaxf(lo + hi, 0.f));
    }
    float* base = g_tmp + ((size_t)bt * Vn + i0) * Vn + j;
    #pragma unroll
    for (int r = 0; r < TR; ++r)
        base[(size_t)r * Vn] = f[r];                      // direct (coalesced)
    // mirror: one aligned float4 per thread -> full 32B sector
    *(float4*)(g_tmp + ((size_t)bt * Vn + j) * Vn + i0) =
        make_float4(f[0], f[1], f[2], f[3]);
}

__global__ __launch_bounds__(256, 3)
void gl_k1(const float* __restrict__ x, const float* __restrict__ a)
{
    extern __shared__ float sm[];
    float* xs  = sm;             // [Vn][PAD]
    float* as_ = sm + SMEM_AS;

    const int tid = threadIdx.x;
    const int bt  = blockIdx.x;
    const int k   = blockIdx.y;                 // pair index 0..31
    const int iA  = k * TR;                     // wide trapezoid (j >= iA)
    const int iB  = (Vn - TR) - k * TR;         // narrow trapezoid (j >= iB)

    // ---- stage x[bt] slice into padded smem ----
    const float4* xp = (const float4*)(x + (size_t)bt * Vn * Fn);
    #pragma unroll
    for (int it = 0; it < 16; ++it) {
        int kk = tid + it * 256;
        float4 v = xp[kk];
        int row = kk >> 4, fc = (kk & 15) << 2;
        *(float4*)&xs[row * PAD + fc] = v;
    }
    if (tid < Fn) as_[tid] = a[tid];
    __syncthreads();

    const int wid = tid >> 5;
    const bool actA = ((wid + 1) << 5) > iA;    // warp-uniform
    const bool actB = ((wid + 1) << 5) > iB;
    if (!actA && !actB) return;

    const uint32_t xs_sh = (uint32_t)__cvta_generic_to_shared(xs);
    const uint32_t as_sh = (uint32_t)__cvta_generic_to_shared(as_);
    const int j = tid;

    u64 accA[TR] = {0,0,0,0}, accB[TR] = {0,0,0,0};

    #pragma unroll 1
    for (int c = 0; c < 4; ++c) {
        const int f0 = c << 4;
        u64 nxj[8], av[8];
        {
            const uint32_t jb = xs_sh + (uint32_t)((j * PAD + f0) * 4);
            u64 t[8];
            lds_2x64(jb +  0, t[0], t[1]);
            lds_2x64(jb + 16, t[2], t[3]);
            lds_2x64(jb + 32, t[4], t[5]);
            lds_2x64(jb + 48, t[6], t[7]);
            #pragma unroll
            for (int q = 0; q < 8; ++q) {
                float lo, hi; unpackf2(t[q], lo, hi);
                nxj[q] = packf2(-lo, -hi);
            }
            const uint32_t ab = as_sh + (uint32_t)(f0 * 4);
            lds_2x64(ab +  0, av[0], av[1]);
            lds_2x64(ab + 16, av[2], av[3]);
            lds_2x64(ab + 32, av[4], av[5]);
            lds_2x64(ab + 48, av[6], av[7]);
        }
        if (actA) tile_rows(xs_sh, iA, f0, nxj, av, accA);
        if (actB) tile_rows(xs_sh, iB, f0, nxj, av, accB);
    }

    if (actA) store_tile(accA, bt, iA, j);
    if (actB) store_tile(accB, bt, iB, j);
}

// K2: warp = 4 rows. 8 front-batched LDG.128 (MLP=8), 4 independent
// butterfly reductions (pipelined SHFLs), 4 rcp, 8 STG.128. No smem/barriers.
__global__ __launch_bounds__(256, 8)
void gl_k2(float* __restrict__ out)
{
    const int tid  = threadIdx.x;
    const int lane = tid & 31;
    const int w    = tid >> 5;
    const int bt   = blockIdx.x;
    const int row0 = (blockIdx.y * 8 + w) * 4;          // 4 consecutive rows

    const float4* rp = (const float4*)(g_tmp + ((size_t)bt * Vn + row0) * Vn);
    float4 v[4][2];
    #pragma unroll
    for (int r = 0; r < 4; ++r) {                        // 8 LDG.128, front-batched
        v[r][0] = rp[(size_t)r * 64 + lane];
        v[r][1] = rp[(size_t)r * 64 + lane + 32];
    }

    float s[4];
    #pragma unroll
    for (int r = 0; r < 4; ++r)
        s[r] = ((v[r][0].x + v[r][0].y) + (v[r][0].z + v[r][0].w))
             + ((v[r][1].x + v[r][1].y) + (v[r][1].z + v[r][1].w));

    #pragma unroll
    for (int m = 16; m >= 1; m >>= 1) {                  // 4 independent chains
        #pragma unroll
        for (int r = 0; r < 4; ++r)
            s[r] += __shfl_xor_sync(0xffffffffu, s[r], m);
    }

    float rc[4];
    #pragma unroll
    for (int r = 0; r < 4; ++r) rc[r] = __fdividef(1.0f, s[r]);

    float4* op = (float4*)(out + ((size_t)bt * Vn + row0) * Vn);
    #pragma unroll
    for (int r = 0; r < 4; ++r) {
        float4 a0 = v[r][0], a1 = v[r][1];
        a0.x *= rc[r]; a0.y *= rc[r]; a0.z *= rc[r]; a0.w *= rc[r];
        a1.x *= rc[r]; a1.y *= rc[r]; a1.z *= rc[r]; a1.w *= rc[r];
        op[(size_t)r * 64 + lane]      = a0;
        op[(size_t)r * 64 + lane + 32] = a1;
    }
}

extern "C" void kernel_launch(void* const* d_in, const int* in_sizes, int n_in,
                              void* d_out, int out_size)
{
    const float* x = (const float*)d_in[0];
    const float* a = (const float*)d_in[1];
    if (n_in >= 2 && in_sizes[0] == Fn && in_sizes[1] > Fn) {
        x = (const float*)d_in[1];
        a = (const float*)d_in[0];
    }
    int bt = in_sizes[0] == Fn ? in_sizes[1] / (Vn * Fn) : in_sizes[0] / (Vn * Fn);

    cudaFuncSetAttribute(gl_k1, cudaFuncAttributeMaxDynamicSharedMemorySize,
                         SMEM_BYTES);
    dim3 g1(bt, Vn / (2 * TR));   // 32 tile-pairs
    gl_k1<<<g1, 256, SMEM_BYTES>>>(x, a);
    dim3 g2(bt, Vn / 32);         // 8 warps x 4 rows = 32 rows per block
    gl_k2<<<g2, 256>>>((float*)d_out);
}